// round 4
// baseline (speedup 1.0000x reference)
#include <cuda_runtime.h>
#include <math.h>

// Problem constants
#define C32    32
#define HW     224
#define BATCH  16
#define NTAPS  288              // 32 ci * 3 * 3
#define TILE_Y 8
#define TILE_X 32
#define SX_H   10               // TILE_Y + 2 halo
#define SX_W   34               // TILE_X + 2 halo

typedef unsigned long long u64;

// Scratch (static device globals; no runtime allocation)
__device__ float g_h[(size_t)BATCH * C32 * HW * HW];   // intermediate h (levels as float)
__device__ float g_w1t[NTAPS * C32];                   // conv1 signed weights, [tap][co]
__device__ float g_w2t[NTAPS * C32];                   // conv2 signed weights, [tap][co]
__device__ float g_t0[64];                             // per-channel threshold base (lut1 | lut2)
__device__ float g_dd[64];                             // per-channel threshold step

// ---- f32x2 packed helpers (ptxas will not auto-fuse; must be inline PTX) ----
__device__ __forceinline__ u64 pack2(float a, float b) {
    u64 r; asm("mov.b64 %0, {%1, %2};" : "=l"(r) : "f"(a), "f"(b)); return r;
}
__device__ __forceinline__ void fma2(u64& d, u64 a, u64 b) {
    asm("fma.rn.f32x2 %0, %1, %2, %0;" : "+l"(d) : "l"(a), "l"(b));
}
__device__ __forceinline__ void unpack2(u64 v, float& lo, float& hi) {
    asm("mov.b64 {%0, %1}, %2;" : "=f"(lo), "=f"(hi) : "l"(v));
}

// ---------------------------------------------------------------------------
// Binarize weights: per output channel, subtract mean over 288 elems, take sign.
// Transposed layout wt[tap*32 + co] so conv reads co-contiguous (LDS.64 pairs).
// ---------------------------------------------------------------------------
__global__ void binarize_kernel(const float* __restrict__ w, float* __restrict__ wt) {
    int co = blockIdx.x;
    int t  = threadIdx.x;  // 0..127
    __shared__ float red[128];
    const float* wc = w + co * NTAPS;

    float v0 = wc[t];
    float v1 = wc[t + 128];
    float v2 = (t < 32) ? wc[t + 256] : 0.0f;
    red[t] = v0 + v1 + v2;
    __syncthreads();
    #pragma unroll
    for (int s = 64; s > 0; s >>= 1) {
        if (t < s) red[t] += red[t + s];
        __syncthreads();
    }
    float mean = red[0] / 288.0f;

    {
        float d = v0 - mean;
        wt[t * C32 + co] = (d > 0.0f) ? 1.0f : ((d < 0.0f) ? -1.0f : 0.0f);
    }
    {
        float d = v1 - mean;
        wt[(t + 128) * C32 + co] = (d > 0.0f) ? 1.0f : ((d < 0.0f) ? -1.0f : 0.0f);
    }
    if (t < 32) {
        float d = v2 - mean;
        wt[(t + 256) * C32 + co] = (d > 0.0f) ? 1.0f : ((d < 0.0f) ? -1.0f : 0.0f);
    }
}

// ---------------------------------------------------------------------------
// Build LUT thresholds (t0 = lut_0, diff = lut_1 - lut_0).
// ---------------------------------------------------------------------------
__global__ void lut_kernel(const float* __restrict__ bw1, const float* __restrict__ bb1,
                           const float* __restrict__ bm1, const float* __restrict__ bv1,
                           const float* __restrict__ bw2, const float* __restrict__ bb2,
                           const float* __restrict__ bm2, const float* __restrict__ bv2,
                           const float* __restrict__ a1p, const float* __restrict__ a2p,
                           const float* __restrict__ nsp) {
    int t = threadIdx.x;   // 0..63
    int c = t & 31;
    float w, b, s1, s2;
    if (t < 32) {
        w  = bw1[c] / sqrtf(bv1[c] + 1e-5f);
        b  = bb1[c] - w * bm1[c];
        s1 = a1p[0];
        s2 = a2p[0];
    } else {
        w  = bw2[c] / sqrtf(bv2[c] + 1e-5f);
        b  = bb2[c] - w * bm2[c];
        s1 = a2p[0];
        s2 = nsp[0];
    }
    float inv = 1.0f / (s1 * w);
    float l0 = rintf((0.5f * s2 - b) * inv);
    float l1 = rintf((1.5f * s2 - b) * inv);
    g_t0[t] = l0;
    g_dd[t] = l1 - l0;
}

// ---------------------------------------------------------------------------
// Fused 3x3 conv (pad 1, stride 1, ±1 weights) + LUT quantization.
// f32x2 packed-FMA version: each thread owns 2 co-PAIRS x 8 px.
//  - packed weight operand  = aligned LDS.64 from s_w[tap][co0..co0+1]  (free)
//  - packed x operand       = (x,x) dup via mov.b64, 10 per (ci,dy) row
// Accumulation order per output identical to scalar version (ci -> dy -> dx).
// ---------------------------------------------------------------------------
__global__ __launch_bounds__(256, 2)
void conv_lut_kernel(const float* __restrict__ in, const float* __restrict__ wt,
                     const float* __restrict__ t0p, const float* __restrict__ ddp,
                     float* __restrict__ out) {
    extern __shared__ float sm[];
    float* s_w = sm;                 // NTAPS*32 = 9216 floats
    float* s_x = sm + NTAPS * C32;   // 32*10*34 = 10880 floats

    int tid = threadIdx.x;
    int b   = blockIdx.z;
    int y0  = blockIdx.y * TILE_Y;
    int x0  = blockIdx.x * TILE_X;

    // Stage weights (vectorized)
    {
        const float4* src = (const float4*)wt;
        float4* dst = (float4*)s_w;
        #pragma unroll
        for (int i = tid; i < NTAPS * C32 / 4; i += 256) dst[i] = src[i];
    }

    // Stage input tile with halo (zero padding)
    const float* inb = in + (size_t)b * C32 * HW * HW;
    for (int i = tid; i < C32 * SX_H * SX_W; i += 256) {
        int ci  = i / (SX_H * SX_W);
        int rem = i % (SX_H * SX_W);
        int ry  = rem / SX_W;
        int cx  = rem % SX_W;
        int gy  = y0 - 1 + ry;
        int gx  = x0 - 1 + cx;
        float v = 0.0f;
        if ((unsigned)gy < (unsigned)HW && (unsigned)gx < (unsigned)HW)
            v = inb[(ci * HW + gy) * HW + gx];
        s_x[i] = v;
    }
    __syncthreads();

    int g   = tid & 7;          // co group 0..7
    int p   = tid >> 3;         // 0..31
    int r   = p >> 2;           // tile row 0..7
    int xc  = (p & 3) * 8;      // tile col chunk {0,8,16,24}
    int co0 = g * 4;

    // acc[pair][px]: pair 0 = (co0,co0+1), pair 1 = (co0+2,co0+3)
    u64 acc[2][8];
    u64 z = pack2(0.0f, 0.0f);
    #pragma unroll
    for (int c = 0; c < 2; c++)
        #pragma unroll
        for (int k = 0; k < 8; k++) acc[c][k] = z;

    const u64* s_w64 = (const u64*)s_w;   // [tap][16 co-pairs]

    for (int ci = 0; ci < C32; ci++) {
        #pragma unroll
        for (int dy = 0; dy < 3; dy++) {
            const float* xr = &s_x[(ci * SX_H + r + dy) * SX_W + xc];
            u64 xd[10];
            #pragma unroll
            for (int k = 0; k < 10; k++) { float v = xr[k]; xd[k] = pack2(v, v); }
            #pragma unroll
            for (int dx = 0; dx < 3; dx++) {
                int tap = (ci * 3 + dy) * 3 + dx;
                u64 w0 = s_w64[tap * 16 + (co0 >> 1)];
                u64 w1 = s_w64[tap * 16 + (co0 >> 1) + 1];
                #pragma unroll
                for (int k = 0; k < 8; k++) {
                    fma2(acc[0][k], w0, xd[k + dx]);
                    fma2(acc[1][k], w1, xd[k + dx]);
                }
            }
        }
    }

    // LUT quantize + store (two float4 stores per co)
    #pragma unroll
    for (int pr = 0; pr < 2; pr++) {
        float a_lo[8], a_hi[8];
        #pragma unroll
        for (int k = 0; k < 8; k++) unpack2(acc[pr][k], a_lo[k], a_hi[k]);
        #pragma unroll
        for (int half = 0; half < 2; half++) {
            int co = co0 + pr * 2 + half;
            const float* av = half ? a_hi : a_lo;
            float t0 = t0p[co];
            float dd = ddp[co];
            float res[8];
            #pragma unroll
            for (int k = 0; k < 8; k++) {
                float v  = av[k];
                int lvl  = 0;
                #pragma unroll
                for (int j = 0; j < 7; j++) {
                    float th = t0 + (float)j * dd;   // exact: integer thresholds
                    lvl += (j & 1) ? (v >= th) : (v > th);   // match >/>= alternation
                }
                res[k] = (float)lvl;
            }
            float* op = out + ((((size_t)b * C32 + co) * HW) + (y0 + r)) * HW + x0 + xc;
            *(float4*)(op + 0) = make_float4(res[0], res[1], res[2], res[3]);
            *(float4*)(op + 4) = make_float4(res[4], res[5], res[6], res[7]);
        }
    }
}

// ---------------------------------------------------------------------------
// Host launcher
// ---------------------------------------------------------------------------
extern "C" void kernel_launch(void* const* d_in, const int* in_sizes, int n_in,
                              void* d_out, int out_size) {
    const float* x   = (const float*)d_in[0];
    const float* w1  = (const float*)d_in[1];
    const float* w2  = (const float*)d_in[2];
    const float* bw1 = (const float*)d_in[3];
    const float* bb1 = (const float*)d_in[4];
    const float* bm1 = (const float*)d_in[5];
    const float* bv1 = (const float*)d_in[6];
    const float* bw2 = (const float*)d_in[7];
    const float* bb2 = (const float*)d_in[8];
    const float* bm2 = (const float*)d_in[9];
    const float* bv2 = (const float*)d_in[10];
    const float* a1  = (const float*)d_in[11];
    const float* a2  = (const float*)d_in[12];
    const float* ns  = (const float*)d_in[13];

    float *hbuf, *w1t, *w2t, *t0, *dd;
    cudaGetSymbolAddress((void**)&hbuf, g_h);
    cudaGetSymbolAddress((void**)&w1t,  g_w1t);
    cudaGetSymbolAddress((void**)&w2t,  g_w2t);
    cudaGetSymbolAddress((void**)&t0,   g_t0);
    cudaGetSymbolAddress((void**)&dd,   g_dd);

    const int smem_bytes = (NTAPS * C32 + C32 * SX_H * SX_W) * sizeof(float);  // 80384
    cudaFuncSetAttribute(conv_lut_kernel, cudaFuncAttributeMaxDynamicSharedMemorySize, smem_bytes);

    binarize_kernel<<<32, 128>>>(w1, w1t);
    binarize_kernel<<<32, 128>>>(w2, w2t);
    lut_kernel<<<1, 64>>>(bw1, bb1, bm1, bv1, bw2, bb2, bm2, bv2, a1, a2, ns);

    dim3 grid(HW / TILE_X, HW / TILE_Y, BATCH);  // (7, 28, 16)
    conv_lut_kernel<<<grid, 256, smem_bytes>>>(x,    w1t, t0,      dd,      hbuf);
    conv_lut_kernel<<<grid, 256, smem_bytes>>>(hbuf, w2t, t0 + 32, dd + 32, (float*)d_out);
}

// round 6
// speedup vs baseline: 2.0459x; 2.0459x over previous
#include <cuda_runtime.h>
#include <math.h>

// Problem constants
#define C32    32
#define HW     224
#define BATCH  16
#define NTAPS  288              // 32 ci * 3 * 3
#define TILE_Y 8
#define TILE_X 32
#define SX_H   10               // TILE_Y + 2 halo
#define SX_W   34               // TILE_X + 2 halo
#define NWORD  8                // 32 ci / 4 per dp4a word

// Scratch (static device globals; no runtime allocation)
__device__ int   g_hp[(size_t)BATCH * NWORD * HW * HW]; // packed h levels (4 ci per int32)
__device__ float g_w1t[NTAPS * C32];                    // conv1 signed weights, [tap][co]
__device__ float g_w2t[NTAPS * C32];                    // conv2 signed weights, [tap][co]
__device__ int   g_w2p[9 * NWORD * C32];                // conv2 packed int8 weights [k][word][co]
__device__ float g_t0[64];                              // per-channel threshold base (lut1 | lut2)
__device__ float g_dd[64];                              // per-channel threshold step

// ---------------------------------------------------------------------------
// Binarize weights: per output channel, subtract mean over 288 elems, take sign.
// Transposed layout wt[tap*32 + co], tap = ci*9 + ky*3 + kx.
// ---------------------------------------------------------------------------
__global__ void binarize_kernel(const float* __restrict__ w, float* __restrict__ wt) {
    int co = blockIdx.x;
    int t  = threadIdx.x;  // 0..127
    __shared__ float red[128];
    const float* wc = w + co * NTAPS;

    float v0 = wc[t];
    float v1 = wc[t + 128];
    float v2 = (t < 32) ? wc[t + 256] : 0.0f;
    red[t] = v0 + v1 + v2;
    __syncthreads();
    #pragma unroll
    for (int s = 64; s > 0; s >>= 1) {
        if (t < s) red[t] += red[t + s];
        __syncthreads();
    }
    float mean = red[0] / 288.0f;

    {
        float d = v0 - mean;
        wt[t * C32 + co] = (d > 0.0f) ? 1.0f : ((d < 0.0f) ? -1.0f : 0.0f);
    }
    {
        float d = v1 - mean;
        wt[(t + 128) * C32 + co] = (d > 0.0f) ? 1.0f : ((d < 0.0f) ? -1.0f : 0.0f);
    }
    if (t < 32) {
        float d = v2 - mean;
        wt[(t + 256) * C32 + co] = (d > 0.0f) ? 1.0f : ((d < 0.0f) ? -1.0f : 0.0f);
    }
}

// ---------------------------------------------------------------------------
// Pack conv2 signed weights into dp4a words: w2p[(k*8 + w8)*32 + co], byte lane
// l holds weight for ci = 4*w8 + l at spatial tap k = ky*3+kx. Values in {-1,0,1}.
// ---------------------------------------------------------------------------
__global__ void pack_w2_kernel(const float* __restrict__ w2t, int* __restrict__ w2p) {
    int i = blockIdx.x * 256 + threadIdx.x;   // 0..2303
    if (i >= 9 * NWORD * C32) return;
    int co = i & 31;
    int w8 = (i >> 5) & 7;
    int k  = i >> 8;                          // 0..8
    unsigned word = 0;
    #pragma unroll
    for (int l = 0; l < 4; l++) {
        int ci = w8 * 4 + l;
        int s  = (int)w2t[(ci * 9 + k) * C32 + co];   // -1, 0, or 1
        word |= ((unsigned)(s & 0xFF)) << (8 * l);
    }
    w2p[(k * NWORD + w8) * C32 + co] = (int)word;
}

// ---------------------------------------------------------------------------
// Build LUT thresholds (t0 = lut_0, diff = lut_1 - lut_0).
// ---------------------------------------------------------------------------
__global__ void lut_kernel(const float* __restrict__ bw1, const float* __restrict__ bb1,
                           const float* __restrict__ bm1, const float* __restrict__ bv1,
                           const float* __restrict__ bw2, const float* __restrict__ bb2,
                           const float* __restrict__ bm2, const float* __restrict__ bv2,
                           const float* __restrict__ a1p, const float* __restrict__ a2p,
                           const float* __restrict__ nsp) {
    int t = threadIdx.x;   // 0..63
    int c = t & 31;
    float w, b, s1, s2;
    if (t < 32) {
        w  = bw1[c] / sqrtf(bv1[c] + 1e-5f);
        b  = bb1[c] - w * bm1[c];
        s1 = a1p[0];
        s2 = a2p[0];
    } else {
        w  = bw2[c] / sqrtf(bv2[c] + 1e-5f);
        b  = bb2[c] - w * bm2[c];
        s1 = a2p[0];
        s2 = nsp[0];
    }
    float inv = 1.0f / (s1 * w);
    float l0 = rintf((0.5f * s2 - b) * inv);
    float l1 = rintf((1.5f * s2 - b) * inv);
    g_t0[t] = l0;
    g_dd[t] = l1 - l0;
}

// ---------------------------------------------------------------------------
// CONV1: fused 3x3 conv (pad 1, stride 1, ±1 fp32 weights) + LUT quantization.
// Identical math/order to the proven R1 kernel (375us, scalar FFMA ceiling).
// Epilogue packs the 4 co-levels per pixel into one int32 (byte per co) and
// stores to the packed h buffer plane g = co0/4.
// ---------------------------------------------------------------------------
__global__ __launch_bounds__(256, 2)
void conv1_lut_kernel(const float* __restrict__ in, const float* __restrict__ wt,
                      const float* __restrict__ t0p, const float* __restrict__ ddp,
                      int* __restrict__ outp) {
    extern __shared__ float sm[];
    float* s_w = sm;                 // NTAPS*32 = 9216 floats
    float* s_x = sm + NTAPS * C32;   // 32*10*34 = 10880 floats

    int tid = threadIdx.x;
    int b   = blockIdx.z;
    int y0  = blockIdx.y * TILE_Y;
    int x0  = blockIdx.x * TILE_X;

    // Stage weights (vectorized)
    {
        const float4* src = (const float4*)wt;
        float4* dst = (float4*)s_w;
        #pragma unroll
        for (int i = tid; i < NTAPS * C32 / 4; i += 256) dst[i] = src[i];
    }

    // Stage input tile with halo (zero padding)
    const float* inb = in + (size_t)b * C32 * HW * HW;
    for (int i = tid; i < C32 * SX_H * SX_W; i += 256) {
        int ci  = i / (SX_H * SX_W);
        int rem = i % (SX_H * SX_W);
        int ry  = rem / SX_W;
        int cx  = rem % SX_W;
        int gy  = y0 - 1 + ry;
        int gx  = x0 - 1 + cx;
        float v = 0.0f;
        if ((unsigned)gy < (unsigned)HW && (unsigned)gx < (unsigned)HW)
            v = inb[(ci * HW + gy) * HW + gx];
        s_x[i] = v;
    }
    __syncthreads();

    int g   = tid & 7;          // co group 0..7  (== packed word plane)
    int p   = tid >> 3;         // 0..31
    int r   = p >> 2;           // tile row 0..7
    int xc  = (p & 3) * 8;      // tile col chunk {0,8,16,24}
    int co0 = g * 4;

    float acc[4][8];
    #pragma unroll
    for (int c = 0; c < 4; c++)
        #pragma unroll
        for (int k = 0; k < 8; k++) acc[c][k] = 0.0f;

    for (int ci = 0; ci < C32; ci++) {
        #pragma unroll
        for (int dy = 0; dy < 3; dy++) {
            const float* xr = &s_x[(ci * SX_H + r + dy) * SX_W + xc];
            float xv[10];
            #pragma unroll
            for (int k = 0; k < 10; k++) xv[k] = xr[k];
            #pragma unroll
            for (int dx = 0; dx < 3; dx++) {
                float4 w4 = *(const float4*)&s_w[((ci * 3 + dy) * 3 + dx) * C32 + co0];
                float wv[4] = {w4.x, w4.y, w4.z, w4.w};
                #pragma unroll
                for (int c = 0; c < 4; c++)
                    #pragma unroll
                    for (int k = 0; k < 8; k++)
                        acc[c][k] = fmaf(wv[c], xv[k + dx], acc[c][k]);
            }
        }
    }

    // LUT quantize -> int levels -> pack 4 cos per pixel into one int32 word
    int lvls[4][8];
    #pragma unroll
    for (int c = 0; c < 4; c++) {
        float t0 = t0p[co0 + c];
        float dd = ddp[co0 + c];
        #pragma unroll
        for (int k = 0; k < 8; k++) {
            float v  = acc[c][k];
            int lvl  = 0;
            #pragma unroll
            for (int j = 0; j < 7; j++) {
                float th = t0 + (float)j * dd;   // exact: integer thresholds
                lvl += (j & 1) ? (v >= th) : (v > th);   // match >/>= alternation
            }
            lvls[c][k] = lvl;
        }
    }
    int words[8];
    #pragma unroll
    for (int k = 0; k < 8; k++)
        words[k] = lvls[0][k] | (lvls[1][k] << 8) | (lvls[2][k] << 16) | (lvls[3][k] << 24);

    int* op = outp + ((((size_t)b * NWORD + g) * HW) + (y0 + r)) * HW + x0 + xc;
    *(int4*)(op + 0) = make_int4(words[0], words[1], words[2], words[3]);
    *(int4*)(op + 4) = make_int4(words[4], words[5], words[6], words[7]);
}

// ---------------------------------------------------------------------------
// CONV2: dp4a int8 conv (exact integer arithmetic, bit-identical to the fp32
// reference given the same h) + LUT quantization, fp32 output.
// Block = (b, 8x32 tile, all 32 co); thread = 4 co x 8 px.
// Per thread: 8 words x 9 taps x 4 co x 8 px = 2304 dp4a (vs 9216 FFMA).
// ---------------------------------------------------------------------------
__global__ __launch_bounds__(256)
void conv2_dp4a_kernel(const int* __restrict__ hp, const int* __restrict__ w2p,
                       const float* __restrict__ t0p, const float* __restrict__ ddp,
                       float* __restrict__ out) {
    __shared__ int s_w[9 * NWORD * C32];       // 2304 words
    __shared__ int s_x[NWORD * SX_H * SX_W];   // 2720 words

    int tid = threadIdx.x;
    int b   = blockIdx.z;
    int y0  = blockIdx.y * TILE_Y;
    int x0  = blockIdx.x * TILE_X;

    // Stage packed weights (vectorized)
    {
        const int4* src = (const int4*)w2p;
        int4* dst = (int4*)s_w;
        #pragma unroll
        for (int i = tid; i < 9 * NWORD * C32 / 4; i += 256) dst[i] = src[i];
    }

    // Stage packed h tile with halo (zero padding)
    const int* hb = hp + (size_t)b * NWORD * HW * HW;
    for (int i = tid; i < NWORD * SX_H * SX_W; i += 256) {
        int w8  = i / (SX_H * SX_W);
        int rem = i % (SX_H * SX_W);
        int ry  = rem / SX_W;
        int cx  = rem % SX_W;
        int gy  = y0 - 1 + ry;
        int gx  = x0 - 1 + cx;
        int v = 0;
        if ((unsigned)gy < (unsigned)HW && (unsigned)gx < (unsigned)HW)
            v = hb[(w8 * HW + gy) * HW + gx];
        s_x[i] = v;
    }
    __syncthreads();

    int g   = tid & 7;
    int p   = tid >> 3;
    int r   = p >> 2;
    int xc  = (p & 3) * 8;
    int co0 = g * 4;

    int acc[4][8];
    #pragma unroll
    for (int c = 0; c < 4; c++)
        #pragma unroll
        for (int k = 0; k < 8; k++) acc[c][k] = 0;

    #pragma unroll
    for (int w8 = 0; w8 < NWORD; w8++) {
        #pragma unroll
        for (int dy = 0; dy < 3; dy++) {
            const int* xr = &s_x[(w8 * SX_H + r + dy) * SX_W + xc];
            int xw[10];
            #pragma unroll
            for (int k = 0; k < 10; k++) xw[k] = xr[k];
            #pragma unroll
            for (int dx = 0; dx < 3; dx++) {
                int tap = dy * 3 + dx;
                int4 w4 = *(const int4*)&s_w[(tap * NWORD + w8) * C32 + co0];
                int wv[4] = {w4.x, w4.y, w4.z, w4.w};
                #pragma unroll
                for (int c = 0; c < 4; c++)
                    #pragma unroll
                    for (int k = 0; k < 8; k++)
                        acc[c][k] = __dp4a(xw[k + dx], wv[c], acc[c][k]);
            }
        }
    }

    // LUT quantize + store (two float4 stores per co)
    #pragma unroll
    for (int c = 0; c < 4; c++) {
        int co   = co0 + c;
        float t0 = t0p[co];
        float dd = ddp[co];
        float res[8];
        #pragma unroll
        for (int k = 0; k < 8; k++) {
            float v  = (float)acc[c][k];      // exact: |acc| <= 2016
            int lvl  = 0;
            #pragma unroll
            for (int j = 0; j < 7; j++) {
                float th = t0 + (float)j * dd;
                lvl += (j & 1) ? (v >= th) : (v > th);
            }
            res[k] = (float)lvl;
        }
        float* op = out + ((((size_t)b * C32 + co) * HW) + (y0 + r)) * HW + x0 + xc;
        *(float4*)(op + 0) = make_float4(res[0], res[1], res[2], res[3]);
        *(float4*)(op + 4) = make_float4(res[4], res[5], res[6], res[7]);
    }
}

// ---------------------------------------------------------------------------
// Host launcher
// ---------------------------------------------------------------------------
extern "C" void kernel_launch(void* const* d_in, const int* in_sizes, int n_in,
                              void* d_out, int out_size) {
    const float* x   = (const float*)d_in[0];
    const float* w1  = (const float*)d_in[1];
    const float* w2  = (const float*)d_in[2];
    const float* bw1 = (const float*)d_in[3];
    const float* bb1 = (const float*)d_in[4];
    const float* bm1 = (const float*)d_in[5];
    const float* bv1 = (const float*)d_in[6];
    const float* bw2 = (const float*)d_in[7];
    const float* bb2 = (const float*)d_in[8];
    const float* bm2 = (const float*)d_in[9];
    const float* bv2 = (const float*)d_in[10];
    const float* a1  = (const float*)d_in[11];
    const float* a2  = (const float*)d_in[12];
    const float* ns  = (const float*)d_in[13];

    float *w1t, *w2t, *t0, *dd;
    int *hp, *w2p;
    cudaGetSymbolAddress((void**)&hp,   g_hp);
    cudaGetSymbolAddress((void**)&w1t,  g_w1t);
    cudaGetSymbolAddress((void**)&w2t,  g_w2t);
    cudaGetSymbolAddress((void**)&w2p,  g_w2p);
    cudaGetSymbolAddress((void**)&t0,   g_t0);
    cudaGetSymbolAddress((void**)&dd,   g_dd);

    const int smem_bytes = (NTAPS * C32 + C32 * SX_H * SX_W) * sizeof(float);  // 80384
    cudaFuncSetAttribute(conv1_lut_kernel, cudaFuncAttributeMaxDynamicSharedMemorySize, smem_bytes);

    binarize_kernel<<<32, 128>>>(w1, w1t);
    binarize_kernel<<<32, 128>>>(w2, w2t);
    pack_w2_kernel<<<9, 256>>>(w2t, w2p);
    lut_kernel<<<1, 64>>>(bw1, bb1, bm1, bv1, bw2, bb2, bm2, bv2, a1, a2, ns);

    dim3 grid(HW / TILE_X, HW / TILE_Y, BATCH);  // (7, 28, 16)
    conv1_lut_kernel<<<grid, 256, smem_bytes>>>(x,  w1t, t0,      dd,      hp);
    conv2_dp4a_kernel<<<grid, 256>>>(hp, w2p, t0 + 32, dd + 32, (float*)d_out);
}